// round 5
// baseline (speedup 1.0000x reference)
#include <cuda_runtime.h>
#include <cstdint>

#define B_   64
#define T_   512
#define D_   256
#define H_   256
#define G4_  1024
#define M_   (B_ * T_)   // 32768

// ---------------- scratch (device globals; no allocations allowed) ----------
__device__ float g_xg[(size_t)M_ * G4_];      // [B][T][4H] gate preacts (128MB)
__device__ float g_y1[(size_t)B_ * T_ * H_];  // layer-1 output (32MB)
__device__ float g_masks[6][B_ * H_];         // [layer*3 + {out,h,c}][B*H]

// ---------------- packed fp32x2 helpers -------------------------------------
#define FMA2(acc, a, b) \
  asm("fma.rn.f32x2 %0, %1, %2, %0;" : "+l"(acc) : "l"(a), "l"(b))
#define PACK2(d, s) \
  asm("mov.b64 %0, {%1, %1};" : "=l"(d) : "f"(s))
#define UNPACK2(lo, hi, s) \
  asm("mov.b64 {%0, %1}, %2;" : "=f"(lo), "=f"(hi) : "l"(s))

__device__ __forceinline__ float fast_sigmoid(float x) {
  return __fdividef(1.f, 1.f + __expf(-x));
}
__device__ __forceinline__ float fast_tanh(float x) {
  float a = fabsf(x);
  float e = __expf(-2.f * a);
  float t = __fdividef(1.f - e, 1.f + e);
  return copysignf(t, x);
}

// ---------------- mbarrier helpers (cluster scope) ---------------------------
#define MBAR_INIT(addr, cnt) \
  asm volatile("mbarrier.init.shared.b64 [%0], %1;" :: "r"(addr), "r"(cnt) : "memory")

#define WAIT_MBAR_CLUSTER(addr, par) do {                                      \
  uint32_t _done;                                                              \
  asm volatile("{\n\t.reg .pred p;\n\t"                                        \
    "mbarrier.try_wait.parity.acquire.cluster.shared::cta.b64 p, [%1], %2;\n\t"\
    "selp.b32 %0, 1, 0, p;\n\t}" : "=r"(_done) : "r"(addr), "r"(par) : "memory"); \
  while (!_done) {                                                             \
    asm volatile("{\n\t.reg .pred p;\n\t"                                      \
      "mbarrier.try_wait.parity.acquire.cluster.shared::cta.b64 p, [%1], %2, 0x989680;\n\t" \
      "selp.b32 %0, 1, 0, p;\n\t}" : "=r"(_done) : "r"(addr), "r"(par) : "memory"); \
  }                                                                            \
} while (0)

__device__ __forceinline__ uint32_t mapa_smem(uint32_t laddr, uint32_t rank) {
  uint32_t ra;
  asm("mapa.shared::cluster.u32 %0, %1, %2;" : "=r"(ra) : "r"(laddr), "r"(rank));
  return ra;
}

// ---------------- threefry2x32 (exact JAX implementation) -------------------
__device__ __forceinline__ void threefry2x32(uint32_t k0, uint32_t k1,
                                             uint32_t x0, uint32_t x1,
                                             uint32_t& o0, uint32_t& o1) {
  uint32_t ks2 = k0 ^ k1 ^ 0x1BD11BDAu;
#define TF_R(rot) { x0 += x1; x1 = (x1 << (rot)) | (x1 >> (32 - (rot))); x1 ^= x0; }
  x0 += k0; x1 += k1;
  TF_R(13) TF_R(15) TF_R(26) TF_R(6)
  x0 += k1;  x1 += ks2 + 1u;
  TF_R(17) TF_R(29) TF_R(16) TF_R(24)
  x0 += ks2; x1 += k0 + 2u;
  TF_R(13) TF_R(15) TF_R(26) TF_R(6)
  x0 += k0;  x1 += k1 + 3u;
  TF_R(17) TF_R(29) TF_R(16) TF_R(24)
  x0 += k1;  x1 += ks2 + 4u;
  TF_R(13) TF_R(15) TF_R(26) TF_R(6)
  x0 += ks2; x1 += k0 + 5u;
#undef TF_R
  o0 = x0; o1 = x1;
}

__device__ __forceinline__ float mask_val(uint32_t bits) {
  float u = __uint_as_float(0x3f800000u | (bits >> 9)) - 1.0f;
  return (u < 0.75f) ? (1.0f / 0.75f) : 0.0f;
}

// Modern JAX (threefry_partitionable=True):
//   split(key, n)[i] = threefry(key, (0, i))
//   random_bits(key,32,shape)[e]: (b1,b2)=threefry(key,(0,e)); bits=b1^b2
__global__ void mask_kernel() {
  int mid   = blockIdx.y;
  int layer = mid / 3, which = mid % 3;
  int e = blockIdx.x * blockDim.x + threadIdx.x;   // 0..16383

  uint32_t Lk0, Lk1, mk0, mk1, b1, b2;
  threefry2x32(0u, 42u, 0u, (uint32_t)layer, Lk0, Lk1);
  threefry2x32(Lk0, Lk1, 0u, (uint32_t)which, mk0, mk1);
  threefry2x32(mk0, mk1, 0u, (uint32_t)e, b1, b2);
  g_masks[mid][e] = mask_val(b1 ^ b2);
}

// ---------------- input-projection GEMM: Y[m][n] = X[m,:]·W[n,:] + bias -----
// X: [M,256] row-major, W: [1024,256] row-major, Y: [M,1024]
__global__ void __launch_bounds__(256, 2) gemm_xg_kernel(
    const float* __restrict__ X, const float* __restrict__ W,
    const float* __restrict__ bi, const float* __restrict__ bh,
    float* __restrict__ Y) {
  const int K = 256, N = 1024;
  __shared__ float As[32][132];   // [kk][mm], padded
  __shared__ float Bs[32][132];   // [kk][nn], padded
  int bm = blockIdx.y * 128, bn = blockIdx.x * 128;
  int tid = threadIdx.x;
  int tx = tid & 15, ty = tid >> 4;

  uint64_t acc[8][4];             // [i][jpair] packed f32x2
#pragma unroll
  for (int i = 0; i < 8; i++)
#pragma unroll
    for (int j = 0; j < 4; j++) acc[i][j] = 0ull;

  for (int k0 = 0; k0 < K; k0 += 32) {
#pragma unroll
    for (int i = 0; i < 4; i++) {
      int idx = tid + i * 256;
      int row = idx >> 3;
      int kk  = (idx & 7) << 2;
      float4 va = *(const float4*)&X[(size_t)(bm + row) * K + k0 + kk];
      As[kk + 0][row] = va.x; As[kk + 1][row] = va.y;
      As[kk + 2][row] = va.z; As[kk + 3][row] = va.w;
      float4 vb = *(const float4*)&W[(size_t)(bn + row) * K + k0 + kk];
      Bs[kk + 0][row] = vb.x; Bs[kk + 1][row] = vb.y;
      Bs[kk + 2][row] = vb.z; Bs[kk + 3][row] = vb.w;
    }
    __syncthreads();
#pragma unroll
    for (int kk = 0; kk < 32; kk++) {
      float4 a0 = *(const float4*)&As[kk][ty * 8];
      float4 a1 = *(const float4*)&As[kk][ty * 8 + 4];
      ulonglong2 b0 = *(const ulonglong2*)&Bs[kk][tx * 8];
      ulonglong2 b1 = *(const ulonglong2*)&Bs[kk][tx * 8 + 4];
      uint64_t ap;
      PACK2(ap, a0.x);
      FMA2(acc[0][0], ap, b0.x); FMA2(acc[0][1], ap, b0.y);
      FMA2(acc[0][2], ap, b1.x); FMA2(acc[0][3], ap, b1.y);
      PACK2(ap, a0.y);
      FMA2(acc[1][0], ap, b0.x); FMA2(acc[1][1], ap, b0.y);
      FMA2(acc[1][2], ap, b1.x); FMA2(acc[1][3], ap, b1.y);
      PACK2(ap, a0.z);
      FMA2(acc[2][0], ap, b0.x); FMA2(acc[2][1], ap, b0.y);
      FMA2(acc[2][2], ap, b1.x); FMA2(acc[2][3], ap, b1.y);
      PACK2(ap, a0.w);
      FMA2(acc[3][0], ap, b0.x); FMA2(acc[3][1], ap, b0.y);
      FMA2(acc[3][2], ap, b1.x); FMA2(acc[3][3], ap, b1.y);
      PACK2(ap, a1.x);
      FMA2(acc[4][0], ap, b0.x); FMA2(acc[4][1], ap, b0.y);
      FMA2(acc[4][2], ap, b1.x); FMA2(acc[4][3], ap, b1.y);
      PACK2(ap, a1.y);
      FMA2(acc[5][0], ap, b0.x); FMA2(acc[5][1], ap, b0.y);
      FMA2(acc[5][2], ap, b1.x); FMA2(acc[5][3], ap, b1.y);
      PACK2(ap, a1.z);
      FMA2(acc[6][0], ap, b0.x); FMA2(acc[6][1], ap, b0.y);
      FMA2(acc[6][2], ap, b1.x); FMA2(acc[6][3], ap, b1.y);
      PACK2(ap, a1.w);
      FMA2(acc[7][0], ap, b0.x); FMA2(acc[7][1], ap, b0.y);
      FMA2(acc[7][2], ap, b1.x); FMA2(acc[7][3], ap, b1.y);
    }
    __syncthreads();
  }

  float bias[8];
#pragma unroll
  for (int j = 0; j < 8; j++) {
    int n = bn + tx * 8 + j;
    bias[j] = bi[n] + bh[n];
  }
#pragma unroll
  for (int i = 0; i < 8; i++) {
    float c[8];
#pragma unroll
    for (int j = 0; j < 4; j++) UNPACK2(c[2 * j], c[2 * j + 1], acc[i][j]);
    size_t base = (size_t)(bm + ty * 8 + i) * N + bn + tx * 8;
    float4 v0 = make_float4(c[0] + bias[0], c[1] + bias[1],
                            c[2] + bias[2], c[3] + bias[3]);
    float4 v1 = make_float4(c[4] + bias[4], c[5] + bias[5],
                            c[6] + bias[6], c[7] + bias[7]);
    *(float4*)&Y[base]     = v0;
    *(float4*)&Y[base + 4] = v1;
  }
}

// ---------------- persistent recurrent LSTM layer ---------------------------
// Cluster of 8 CTAs per 4 batch elements. CTA rank s owns hidden units
// [32s, 32s+32) for all 4 gates (128 weight rows, smem-resident, [k][r] layout).
// Sync: per-source mbarriers (no barrier.cluster in the loop). mbar[s] in each
// CTA receives 4 arrivals/step from CTA s's finalize warps; a consumer thread
// with k-quarter kq waits only on mbar[2kq], mbar[2kq+1].
#define LSTM_W_FLOATS    (256 * 129)
#define LSTM_H_FLOATS    (2 * 256 * 4)
#define LSTM_P_FLOATS    (4 * 128 * 4)
#define LSTM_FLOATS      (LSTM_W_FLOATS + LSTM_H_FLOATS + LSTM_P_FLOATS)
#define LSTM_SMEM_BYTES  (LSTM_FLOATS * 4 + 64)   // + 8 mbarriers

__global__ void __launch_bounds__(512, 1) __cluster_dims__(8, 1, 1)
lstm_layer_kernel(const float* __restrict__ xg, const float* __restrict__ Whh,
                  const float* __restrict__ mask_out,
                  const float* __restrict__ mask_h,
                  const float* __restrict__ mask_c,
                  float* __restrict__ out) {
  extern __shared__ float smem[];
  float* wT   = smem;                       // [256][129] (k-major, pad 129)
  float* hbuf = wT + LSTM_W_FLOATS;         // [2][256][4]
  float* part = hbuf + LSTM_H_FLOATS;       // [4][128][4]
  uint32_t smem_u32 = (uint32_t)__cvta_generic_to_shared(smem);
  uint32_t mbar0 = smem_u32 + LSTM_FLOATS * 4;   // 8 x u64

  int tid = threadIdx.x;
  uint32_t s;
  asm("mov.u32 %0, %%cluster_ctarank;" : "=r"(s));
  int b_base = (blockIdx.x >> 3) * 4;

  int kq = tid >> 7;          // k-quarter 0..3
  int r  = tid & 127;         // local gate-row (gate = r>>5, unit = r&31)
  uint32_t mb_w0 = mbar0 + (uint32_t)(2 * kq) * 8;       // wait barriers
  uint32_t mb_w1 = mb_w0 + 8;

  if (tid == 0) {
#pragma unroll
    for (int i = 0; i < 8; i++) MBAR_INIT(mbar0 + i * 8, 4);
  }

  // load weight slice transposed into smem
  for (int idx = tid; idx < 128 * 256; idx += 512) {
    int rr = idx >> 8;
    int k  = idx & 255;
    int gr = ((rr >> 5) << 8) + ((int)s << 5) + (rr & 31);
    wT[k * 129 + rr] = Whh[(size_t)gr * 256 + k];
  }
  for (int idx = tid; idx < 2 * 256 * 4; idx += 512) hbuf[idx] = 0.f;

  // finalize-role (tid < 128): one (unit u, batch b) pair each
  float c_state = 0.f, mo = 0.f, mh = 0.f, mc = 0.f;
  int u = tid >> 2;
  size_t out_base = 0;
  const float* xg_base = nullptr;
  uint32_t haddr[2][8];
  uint32_t arrAddr[8];
  if (tid < 128) {
    int b = tid & 3;
    int bb = b_base + b;
    int unit = (int)s * 32 + u;
    mo = mask_out[bb * 256 + unit];
    mh = mask_h  [bb * 256 + unit];
    mc = mask_c  [bb * 256 + unit];
    out_base = (size_t)bb * (T_ * H_) + unit;
    xg_base  = xg + (size_t)bb * (T_ * G4_) + unit;
    uint32_t hb_u32 = smem_u32 + (uint32_t)LSTM_W_FLOATS * 4;
#pragma unroll
    for (int par = 0; par < 2; par++) {
      uint32_t laddr = hb_u32 + (uint32_t)(par * 1024 + unit * 4 + b) * 4;
#pragma unroll
      for (int rk = 0; rk < 8; rk++) haddr[par][rk] = mapa_smem(laddr, rk);
    }
    uint32_t my_mbar = mbar0 + s * 8;        // this CTA's source barrier slot
#pragma unroll
    for (int rk = 0; rk < 8; rk++) arrAddr[rk] = mapa_smem(my_mbar, rk);
  }

  asm volatile("barrier.cluster.arrive.aligned;" ::: "memory");
  asm volatile("barrier.cluster.wait.aligned;"   ::: "memory");

  const float* wk = wT + (kq * 64) * 129 + r;

  for (int t = 0; t < T_; t++) {
    int par = t & 1;
    // prefetch this step's gate preacts (finalize threads), before any wait
    float xvi = 0.f, xvf = 0.f, xvg = 0.f, xvo = 0.f;
    if (tid < 128) {
      const float* xp = xg_base + (size_t)t * G4_;
      xvi = xp[0];
      xvf = xp[256];
      xvg = xp[512];
      xvo = xp[768];
    }

    // wait for this step's h from the two source CTAs this k-quarter reads
    if (t > 0) {
      int p = (t - 1) & 1;
      WAIT_MBAR_CLUSTER(mb_w0, p);
      WAIT_MBAR_CLUSTER(mb_w1, p);
    }

    // partial dot over this thread's k-quarter (64 k), 4 batches packed f32x2
    const ulonglong2* hb =
        (const ulonglong2*)(hbuf + par * 1024 + kq * 256);
    uint64_t a01 = 0ull, a23 = 0ull;
#pragma unroll 8
    for (int k0 = 0; k0 < 64; k0++) {
      float w = wk[k0 * 129];
      uint64_t wd;
      PACK2(wd, w);
      ulonglong2 h2 = hb[k0];
      FMA2(a01, wd, h2.x);
      FMA2(a23, wd, h2.y);
    }
    *(ulonglong2*)&part[(kq * 128 + r) * 4] = make_ulonglong2(a01, a23);
    __syncthreads();

    if (tid < 128) {
      int b = tid & 3;
      float gi = xvi, gf = xvf, gg = xvg, go = xvo;
#pragma unroll
      for (int q2 = 0; q2 < 4; q2++) {
        const float* pp = part + q2 * 512;
        gi += pp[(u)      * 4 + b];
        gf += pp[(32 + u) * 4 + b];
        gg += pp[(64 + u) * 4 + b];
        go += pp[(96 + u) * 4 + b];
      }
      float ig = fast_sigmoid(gi);
      float fg = fast_sigmoid(gf);
      float og = fast_sigmoid(go);
      float gt = fast_tanh(gg);
      c_state = fg * c_state + ig * gt;
      float h = og * fast_tanh(c_state);
      c_state *= mc;                            // variational cell mask
      out[out_base + (size_t)t * H_] = h * mo;  // output mask
      float hm = h * mh;                        // carry mask
#pragma unroll
      for (int rk = 0; rk < 8; rk++)
        asm volatile("st.shared::cluster.f32 [%0], %1;"
                     :: "r"(haddr[par ^ 1][rk]), "f"(hm) : "memory");
      __syncwarp();
      if ((tid & 31) == 0) {
        asm volatile("fence.acq_rel.cluster;" ::: "memory");
#pragma unroll
        for (int rk = 0; rk < 8; rk++)
          asm volatile(
              "mbarrier.arrive.relaxed.cluster.shared::cluster.b64 _, [%0];"
              :: "r"(arrAddr[rk]) : "memory");
      }
    }
    __syncthreads();   // protect 'part' from next step's overwrite
  }

  asm volatile("barrier.cluster.arrive.aligned;" ::: "memory");
  asm volatile("barrier.cluster.wait.aligned;"   ::: "memory");
}

// ---------------- launcher ---------------------------------------------------
extern "C" void kernel_launch(void* const* d_in, const int* in_sizes, int n_in,
                              void* d_out, int out_size) {
  const float* x     = (const float*)d_in[0];
  const float* W_ih0 = (const float*)d_in[1];
  const float* W_hh0 = (const float*)d_in[2];
  const float* b_ih0 = (const float*)d_in[3];
  const float* b_hh0 = (const float*)d_in[4];
  const float* W_ih1 = (const float*)d_in[5];
  const float* W_hh1 = (const float*)d_in[6];
  const float* b_ih1 = (const float*)d_in[7];
  const float* b_hh1 = (const float*)d_in[8];
  float* out = (float*)d_out;

  float *xg, *y1, *masks;
  cudaGetSymbolAddress((void**)&xg, g_xg);
  cudaGetSymbolAddress((void**)&y1, g_y1);
  cudaGetSymbolAddress((void**)&masks, g_masks);

  cudaFuncSetAttribute(lstm_layer_kernel,
                       cudaFuncAttributeMaxDynamicSharedMemorySize,
                       LSTM_SMEM_BYTES);

  mask_kernel<<<dim3(64, 6), 256>>>();

  gemm_xg_kernel<<<dim3(8, 256), 256>>>(x, W_ih0, b_ih0, b_hh0, xg);
  lstm_layer_kernel<<<128, 512, LSTM_SMEM_BYTES>>>(
      xg, W_hh0, masks + 0 * 16384, masks + 1 * 16384, masks + 2 * 16384, y1);

  gemm_xg_kernel<<<dim3(8, 256), 256>>>(y1, W_ih1, b_ih1, b_hh1, xg);
  lstm_layer_kernel<<<128, 512, LSTM_SMEM_BYTES>>>(
      xg, W_hh1, masks + 3 * 16384, masks + 4 * 16384, masks + 5 * 16384, out);
}

// round 6
// speedup vs baseline: 1.1795x; 1.1795x over previous
#include <cuda_runtime.h>
#include <cstdint>

#define B_   64
#define T_   512
#define D_   256
#define H_   256
#define G4_  1024
#define M_   (B_ * T_)   // 32768

// ---------------- scratch (device globals; no allocations allowed) ----------
__device__ float g_xg[(size_t)M_ * G4_];      // [B][T][4H] gate preacts (128MB)
__device__ float g_y1[(size_t)B_ * T_ * H_];  // layer-1 output (32MB)
__device__ float g_masks[6][B_ * H_];         // [layer*3 + {out,h,c}][B*H]

// ---------------- packed fp32x2 helpers -------------------------------------
#define FMA2(acc, a, b) \
  asm("fma.rn.f32x2 %0, %1, %2, %0;" : "+l"(acc) : "l"(a), "l"(b))
#define ADD2(d, a, b) \
  asm("add.rn.f32x2 %0, %1, %2;" : "=l"(d) : "l"(a), "l"(b))
#define PACKD(d, s) \
  asm("mov.b64 %0, {%1, %1};" : "=l"(d) : "f"(s))
#define PACK2V(d, lo, hi) \
  asm("mov.b64 %0, {%1, %2};" : "=l"(d) : "f"(lo), "f"(hi))
#define UNPACK2(lo, hi, s) \
  asm("mov.b64 {%0, %1}, %2;" : "=f"(lo), "=f"(hi) : "l"(s))

__device__ __forceinline__ float fast_sigmoid(float x) {
  return __fdividef(1.f, 1.f + __expf(-x));
}
__device__ __forceinline__ float fast_tanh(float x) {
  float a = fabsf(x);
  float e = __expf(-2.f * a);
  float t = __fdividef(1.f - e, 1.f + e);
  return copysignf(t, x);
}

// ---------------- threefry2x32 (exact JAX implementation) -------------------
__device__ __forceinline__ void threefry2x32(uint32_t k0, uint32_t k1,
                                             uint32_t x0, uint32_t x1,
                                             uint32_t& o0, uint32_t& o1) {
  uint32_t ks2 = k0 ^ k1 ^ 0x1BD11BDAu;
#define TF_R(rot) { x0 += x1; x1 = (x1 << (rot)) | (x1 >> (32 - (rot))); x1 ^= x0; }
  x0 += k0; x1 += k1;
  TF_R(13) TF_R(15) TF_R(26) TF_R(6)
  x0 += k1;  x1 += ks2 + 1u;
  TF_R(17) TF_R(29) TF_R(16) TF_R(24)
  x0 += ks2; x1 += k0 + 2u;
  TF_R(13) TF_R(15) TF_R(26) TF_R(6)
  x0 += k0;  x1 += k1 + 3u;
  TF_R(17) TF_R(29) TF_R(16) TF_R(24)
  x0 += k1;  x1 += ks2 + 4u;
  TF_R(13) TF_R(15) TF_R(26) TF_R(6)
  x0 += ks2; x1 += k0 + 5u;
#undef TF_R
  o0 = x0; o1 = x1;
}

__device__ __forceinline__ float mask_val(uint32_t bits) {
  float u = __uint_as_float(0x3f800000u | (bits >> 9)) - 1.0f;
  return (u < 0.75f) ? (1.0f / 0.75f) : 0.0f;
}

// Modern JAX (threefry_partitionable=True):
//   split(key, n)[i] = threefry(key, (0, i))
//   random_bits(key,32,shape)[e]: (b1,b2)=threefry(key,(0,e)); bits=b1^b2
__global__ void mask_kernel() {
  int mid   = blockIdx.y;
  int layer = mid / 3, which = mid % 3;
  int e = blockIdx.x * blockDim.x + threadIdx.x;   // 0..16383

  uint32_t Lk0, Lk1, mk0, mk1, b1, b2;
  threefry2x32(0u, 42u, 0u, (uint32_t)layer, Lk0, Lk1);
  threefry2x32(Lk0, Lk1, 0u, (uint32_t)which, mk0, mk1);
  threefry2x32(mk0, mk1, 0u, (uint32_t)e, b1, b2);
  g_masks[mid][e] = mask_val(b1 ^ b2);
}

// ---------------- input-projection GEMM: Y[m][n] = X[m,:]·W[n,:] + bias -----
__global__ void __launch_bounds__(256, 2) gemm_xg_kernel(
    const float* __restrict__ X, const float* __restrict__ W,
    const float* __restrict__ bi, const float* __restrict__ bh,
    float* __restrict__ Y) {
  const int K = 256, N = 1024;
  __shared__ float As[32][132];
  __shared__ float Bs[32][132];
  int bm = blockIdx.y * 128, bn = blockIdx.x * 128;
  int tid = threadIdx.x;
  int tx = tid & 15, ty = tid >> 4;

  uint64_t acc[8][4];
#pragma unroll
  for (int i = 0; i < 8; i++)
#pragma unroll
    for (int j = 0; j < 4; j++) acc[i][j] = 0ull;

  for (int k0 = 0; k0 < K; k0 += 32) {
#pragma unroll
    for (int i = 0; i < 4; i++) {
      int idx = tid + i * 256;
      int row = idx >> 3;
      int kk  = (idx & 7) << 2;
      float4 va = *(const float4*)&X[(size_t)(bm + row) * K + k0 + kk];
      As[kk + 0][row] = va.x; As[kk + 1][row] = va.y;
      As[kk + 2][row] = va.z; As[kk + 3][row] = va.w;
      float4 vb = *(const float4*)&W[(size_t)(bn + row) * K + k0 + kk];
      Bs[kk + 0][row] = vb.x; Bs[kk + 1][row] = vb.y;
      Bs[kk + 2][row] = vb.z; Bs[kk + 3][row] = vb.w;
    }
    __syncthreads();
#pragma unroll
    for (int kk = 0; kk < 32; kk++) {
      float4 a0 = *(const float4*)&As[kk][ty * 8];
      float4 a1 = *(const float4*)&As[kk][ty * 8 + 4];
      ulonglong2 b0 = *(const ulonglong2*)&Bs[kk][tx * 8];
      ulonglong2 b1 = *(const ulonglong2*)&Bs[kk][tx * 8 + 4];
      float av[8] = {a0.x, a0.y, a0.z, a0.w, a1.x, a1.y, a1.z, a1.w};
#pragma unroll
      for (int i = 0; i < 8; i++) {
        uint64_t ap;
        PACKD(ap, av[i]);
        FMA2(acc[i][0], ap, b0.x);
        FMA2(acc[i][1], ap, b0.y);
        FMA2(acc[i][2], ap, b1.x);
        FMA2(acc[i][3], ap, b1.y);
      }
    }
    __syncthreads();
  }

  float bias[8];
#pragma unroll
  for (int j = 0; j < 8; j++) {
    int n = bn + tx * 8 + j;
    bias[j] = bi[n] + bh[n];
  }
#pragma unroll
  for (int i = 0; i < 8; i++) {
    float c[8];
#pragma unroll
    for (int j = 0; j < 4; j++) UNPACK2(c[2 * j], c[2 * j + 1], acc[i][j]);
    size_t base = (size_t)(bm + ty * 8 + i) * N + bn + tx * 8;
    float4 v0 = make_float4(c[0] + bias[0], c[1] + bias[1],
                            c[2] + bias[2], c[3] + bias[3]);
    float4 v1 = make_float4(c[4] + bias[4], c[5] + bias[5],
                            c[6] + bias[6], c[7] + bias[7]);
    *(float4*)&Y[base]     = v0;
    *(float4*)&Y[base + 4] = v1;
  }
}

// ---------------- persistent recurrent LSTM layer ---------------------------
// Cluster of 8 CTAs per 4 batch elements. CTA rank s owns gate-rows
// g*256 + 32s + [0,32) for the 4 gates (128 rows). Weights live in REGISTERS:
// thread (rq = tid>>4, ks = tid&15) holds rows 4rq..4rq+3 (packed row-pairs)
// for k-slice [16ks, 16ks+16). Per step: 16x(LDS.128 h + 8 FFMA2), butterfly
// shuffle-reduce over the 16 ks lanes, finalize, wide DSMEM h broadcast,
// one barrier.cluster.
#define HB_STRIDE 1088     // 256 k * 4 batch + pad 4 floats per 16 k

__device__ __forceinline__ int hoff(int k) {   // float offset of h[k][b=0]
  return k * 4 + (k >> 4) * 4;
}

__global__ void __launch_bounds__(512, 1) __cluster_dims__(8, 1, 1)
lstm_layer_kernel(const float* __restrict__ xg, const float* __restrict__ Whh,
                  const float* __restrict__ mask_out,
                  const float* __restrict__ mask_h,
                  const float* __restrict__ mask_c,
                  float* __restrict__ out) {
  __shared__ float hbuf[2 * HB_STRIDE];   // [par][k padded][4 b]
  __shared__ float part[4 * 128];         // [b][row]
  __shared__ float hstage[32 * 4];        // [unit][b]

  int tid = threadIdx.x;
  uint32_t s;
  asm("mov.u32 %0, %%cluster_ctarank;" : "=r"(s));
  int b_base = (blockIdx.x >> 3) * 4;

  int ks = tid & 15;          // k-slice  (k in [16ks, 16ks+16))
  int rq = tid >> 4;          // row-quad (rows 4rq..4rq+3)

  // ---- load this thread's weight tile into registers (packed row-pairs) ----
  uint64_t wp[2][16];
  {
    float wrow[4][16];
#pragma unroll
    for (int j = 0; j < 4; j++) {
      int r = 4 * rq + j;
      int grow = ((r >> 5) << 8) + ((int)s << 5) + (r & 31);
      const float4* wsrc = (const float4*)(Whh + (size_t)grow * 256 + ks * 16);
#pragma unroll
      for (int q = 0; q < 4; q++) {
        float4 v = wsrc[q];
        wrow[j][q * 4 + 0] = v.x; wrow[j][q * 4 + 1] = v.y;
        wrow[j][q * 4 + 2] = v.z; wrow[j][q * 4 + 3] = v.w;
      }
    }
#pragma unroll
    for (int rp = 0; rp < 2; rp++)
#pragma unroll
      for (int kk = 0; kk < 16; kk++)
        PACK2V(wp[rp][kk], wrow[2 * rp][kk], wrow[2 * rp + 1][kk]);
  }

  for (int idx = tid; idx < 2 * HB_STRIDE; idx += 512) hbuf[idx] = 0.f;

  // ---- finalize-role state (tid < 128): one (unit u, batch b) each --------
  float c_state = 0.f, mo = 0.f, mh = 0.f, mc = 0.f;
  int u = tid >> 2;
  size_t out_base = 0;
  const float* xg_base = nullptr;
  if (tid < 128) {
    int b = tid & 3;
    int bb = b_base + b;
    int unit = (int)s * 32 + u;
    mo = mask_out[bb * 256 + unit];
    mh = mask_h  [bb * 256 + unit];
    mc = mask_c  [bb * 256 + unit];
    out_base = (size_t)bb * (T_ * H_) + unit;
    xg_base  = xg + (size_t)bb * (T_ * G4_) + unit;
  }

  // remote-copy role: warp w covers local units 8w..8w+7; lane handles
  // 2 tasks (unit, rank)
  uint32_t hbuf_u32 = (uint32_t)__cvta_generic_to_shared(hbuf);
  uint32_t cp_raddr[2][2];    // [par][task]
  uint32_t cp_src[2];
  if (tid < 128) {
    int w = tid >> 5, lane = tid & 31;
#pragma unroll
    for (int task = 0; task < 2; task++) {
      int tsk  = lane + task * 32;            // 0..63
      int unit = w * 8 + (tsk >> 3);          // local unit
      int rk   = tsk & 7;                     // dest rank
      int gk   = (int)s * 32 + unit;          // global hidden index
      cp_src[task] = (uint32_t)__cvta_generic_to_shared(&hstage[unit * 4]);
#pragma unroll
      for (int par = 0; par < 2; par++) {
        uint32_t laddr = hbuf_u32 + (uint32_t)(par * HB_STRIDE + hoff(gk)) * 4;
        uint32_t ra;
        asm("mapa.shared::cluster.u32 %0, %1, %2;"
            : "=r"(ra) : "r"(laddr), "r"((uint32_t)rk));
        cp_raddr[par][task] = ra;
      }
    }
  }

  asm volatile("barrier.cluster.arrive.aligned;" ::: "memory");
  asm volatile("barrier.cluster.wait.aligned;"   ::: "memory");

  for (int t = 0; t < T_; t++) {
    int par = t & 1;
    // prefetch gate preacts (finalize threads), hidden behind the matmul
    float xvi = 0.f, xvf = 0.f, xvg = 0.f, xvo = 0.f;
    if (tid < 128) {
      const float* xp = xg_base + (size_t)t * G4_;
      xvi = xp[0];
      xvf = xp[256];
      xvg = xp[512];
      xvo = xp[768];
    }

    // ---- register-resident matmul: rows 4rq..+3, k in [16ks,16ks+16) ------
    uint64_t acc[2][4];
#pragma unroll
    for (int rp = 0; rp < 2; rp++)
#pragma unroll
      for (int b = 0; b < 4; b++) acc[rp][b] = 0ull;

    const float4* hb4 = (const float4*)(hbuf + par * HB_STRIDE + ks * 68);
#pragma unroll
    for (int kk = 0; kk < 16; kk++) {
      float4 hv = hb4[kk];
      uint64_t h0, h1, h2, h3;
      PACKD(h0, hv.x); PACKD(h1, hv.y); PACKD(h2, hv.z); PACKD(h3, hv.w);
      FMA2(acc[0][0], wp[0][kk], h0);
      FMA2(acc[1][0], wp[1][kk], h0);
      FMA2(acc[0][1], wp[0][kk], h1);
      FMA2(acc[1][1], wp[1][kk], h1);
      FMA2(acc[0][2], wp[0][kk], h2);
      FMA2(acc[1][2], wp[1][kk], h2);
      FMA2(acc[0][3], wp[0][kk], h3);
      FMA2(acc[1][3], wp[1][kk], h3);
    }

    // ---- butterfly reduce over the 16 ks lanes (within half-warp) ---------
#pragma unroll
    for (int m = 8; m >= 1; m >>= 1) {
#pragma unroll
      for (int rp = 0; rp < 2; rp++)
#pragma unroll
        for (int b = 0; b < 4; b++) {
          uint64_t o = __shfl_xor_sync(0xFFFFFFFFu, acc[rp][b], m);
          ADD2(acc[rp][b], acc[rp][b], o);
        }
    }
    if (ks == 0) {
      uint64_t* pp = (uint64_t*)part;
#pragma unroll
      for (int b = 0; b < 4; b++) {
        pp[b * 64 + 2 * rq + 0] = acc[0][b];   // rows 4rq, 4rq+1
        pp[b * 64 + 2 * rq + 1] = acc[1][b];   // rows 4rq+2, 4rq+3
      }
    }
    __syncthreads();

    // ---- finalize + wide DSMEM broadcast ----------------------------------
    if (tid < 128) {
      int b = tid & 3;
      const float* pb = part + b * 128;
      float gi = xvi + pb[u];
      float gf = xvf + pb[32 + u];
      float gg = xvg + pb[64 + u];
      float go = xvo + pb[96 + u];
      float ig = fast_sigmoid(gi);
      float fg = fast_sigmoid(gf);
      float og = fast_sigmoid(go);
      float gt = fast_tanh(gg);
      c_state = fg * c_state + ig * gt;
      float h = og * fast_tanh(c_state);
      c_state *= mc;                            // variational cell mask
      out[out_base + (size_t)t * H_] = h * mo;  // output mask
      hstage[u * 4 + b] = h * mh;               // carry mask, staged
      __syncwarp();
      int pn = par ^ 1;
#pragma unroll
      for (int task = 0; task < 2; task++) {
        float4 hv = *(const float4*)__cvta_shared_to_generic((size_t)cp_src[task]);
        asm volatile("st.shared::cluster.v4.f32 [%0], {%1,%2,%3,%4};"
                     :: "r"(cp_raddr[pn][task]),
                        "f"(hv.x), "f"(hv.y), "f"(hv.z), "f"(hv.w) : "memory");
      }
    }
    asm volatile("barrier.cluster.arrive.aligned;" ::: "memory");
    asm volatile("barrier.cluster.wait.aligned;"   ::: "memory");
  }

  asm volatile("barrier.cluster.arrive.aligned;" ::: "memory");
  asm volatile("barrier.cluster.wait.aligned;"   ::: "memory");
}

// ---------------- launcher ---------------------------------------------------
extern "C" void kernel_launch(void* const* d_in, const int* in_sizes, int n_in,
                              void* d_out, int out_size) {
  const float* x     = (const float*)d_in[0];
  const float* W_ih0 = (const float*)d_in[1];
  const float* W_hh0 = (const float*)d_in[2];
  const float* b_ih0 = (const float*)d_in[3];
  const float* b_hh0 = (const float*)d_in[4];
  const float* W_ih1 = (const float*)d_in[5];
  const float* W_hh1 = (const float*)d_in[6];
  const float* b_ih1 = (const float*)d_in[7];
  const float* b_hh1 = (const float*)d_in[8];
  float* out = (float*)d_out;

  float *xg, *y1, *masks;
  cudaGetSymbolAddress((void**)&xg, g_xg);
  cudaGetSymbolAddress((void**)&y1, g_y1);
  cudaGetSymbolAddress((void**)&masks, g_masks);

  mask_kernel<<<dim3(64, 6), 256>>>();

  gemm_xg_kernel<<<dim3(8, 256), 256>>>(x, W_ih0, b_ih0, b_hh0, xg);
  lstm_layer_kernel<<<128, 512>>>(
      xg, W_hh0, masks + 0 * 16384, masks + 1 * 16384, masks + 2 * 16384, y1);

  gemm_xg_kernel<<<dim3(8, 256), 256>>>(y1, W_ih1, b_ih1, b_hh1, xg);
  lstm_layer_kernel<<<128, 512>>>(
      xg, W_hh1, masks + 3 * 16384, masks + 4 * 16384, masks + 5 * 16384, out);
}

// round 8
// speedup vs baseline: 1.2234x; 1.0372x over previous
#include <cuda_runtime.h>
#include <cstdint>

#define B_   64
#define T_   512
#define D_   256
#define H_   256
#define G4_  1024
#define M_   (B_ * T_)   // 32768

// ---------------- scratch (device globals; no allocations allowed) ----------
__device__ float g_xg[(size_t)M_ * G4_];      // [B][T][4H] gate preacts
__device__ float g_y1[(size_t)B_ * T_ * H_];  // layer-1 output
__device__ float g_masks[6][B_ * H_];         // [layer*3 + {out,h,c}][B*H]

// ---------------- packed fp32x2 helpers -------------------------------------
#define FMA2(acc, a, b) \
  asm("fma.rn.f32x2 %0, %1, %2, %0;" : "+l"(acc) : "l"(a), "l"(b))
#define ADD2(d, a, b) \
  asm("add.rn.f32x2 %0, %1, %2;" : "=l"(d) : "l"(a), "l"(b))
#define PACKD(d, s) \
  asm("mov.b64 %0, {%1, %1};" : "=l"(d) : "f"(s))
#define PACK2V(d, lo, hi) \
  asm("mov.b64 %0, {%1, %2};" : "=l"(d) : "f"(lo), "f"(hi))
#define UNPACK2(lo, hi, s) \
  asm("mov.b64 {%0, %1}, %2;" : "=f"(lo), "=f"(hi) : "l"(s))

__device__ __forceinline__ float fast_sigmoid(float x) {
  return __fdividef(1.f, 1.f + __expf(-x));
}
__device__ __forceinline__ float fast_tanh(float x) {
  float a = fabsf(x);
  float e = __expf(-2.f * a);
  float t = __fdividef(1.f - e, 1.f + e);
  return copysignf(t, x);
}

// ---------------- mbarrier helpers -------------------------------------------
#define MBAR_INIT(addr, cnt) \
  asm volatile("mbarrier.init.shared.b64 [%0], %1;" :: "r"(addr), "r"(cnt) : "memory")

#define MBAR_EXPECT(addr, bytes) \
  asm volatile("mbarrier.arrive.expect_tx.shared.b64 _, [%0], %1;" \
               :: "r"(addr), "r"(bytes) : "memory")

#define WAIT_MBAR(addr, par) do {                                              \
  uint32_t _done;                                                              \
  asm volatile("{\n\t.reg .pred p;\n\t"                                        \
    "mbarrier.try_wait.parity.acquire.cluster.shared::cta.b64 p, [%1], %2;\n\t"\
    "selp.b32 %0, 1, 0, p;\n\t}" : "=r"(_done) : "r"(addr), "r"(par) : "memory"); \
  while (!_done) {                                                             \
    asm volatile("{\n\t.reg .pred p;\n\t"                                      \
      "mbarrier.try_wait.parity.acquire.cluster.shared::cta.b64 p, [%1], %2, 0x989680;\n\t" \
      "selp.b32 %0, 1, 0, p;\n\t}" : "=r"(_done) : "r"(addr), "r"(par) : "memory"); \
  }                                                                            \
} while (0)

__device__ __forceinline__ uint32_t mapa_smem(uint32_t laddr, uint32_t rank) {
  uint32_t ra;
  asm("mapa.shared::cluster.u32 %0, %1, %2;" : "=r"(ra) : "r"(laddr), "r"(rank));
  return ra;
}

// ---------------- threefry2x32 (exact JAX implementation) -------------------
__device__ __forceinline__ void threefry2x32(uint32_t k0, uint32_t k1,
                                             uint32_t x0, uint32_t x1,
                                             uint32_t& o0, uint32_t& o1) {
  uint32_t ks2 = k0 ^ k1 ^ 0x1BD11BDAu;
#define TF_R(rot) { x0 += x1; x1 = (x1 << (rot)) | (x1 >> (32 - (rot))); x1 ^= x0; }
  x0 += k0; x1 += k1;
  TF_R(13) TF_R(15) TF_R(26) TF_R(6)
  x0 += k1;  x1 += ks2 + 1u;
  TF_R(17) TF_R(29) TF_R(16) TF_R(24)
  x0 += ks2; x1 += k0 + 2u;
  TF_R(13) TF_R(15) TF_R(26) TF_R(6)
  x0 += k0;  x1 += k1 + 3u;
  TF_R(17) TF_R(29) TF_R(16) TF_R(24)
  x0 += k1;  x1 += ks2 + 4u;
  TF_R(13) TF_R(15) TF_R(26) TF_R(6)
  x0 += ks2; x1 += k0 + 5u;
#undef TF_R
  o0 = x0; o1 = x1;
}

__device__ __forceinline__ float mask_val(uint32_t bits) {
  float u = __uint_as_float(0x3f800000u | (bits >> 9)) - 1.0f;
  return (u < 0.75f) ? (1.0f / 0.75f) : 0.0f;
}

__global__ void mask_kernel() {
  int mid   = blockIdx.y;
  int layer = mid / 3, which = mid % 3;
  int e = blockIdx.x * blockDim.x + threadIdx.x;   // 0..16383

  uint32_t Lk0, Lk1, mk0, mk1, b1, b2;
  threefry2x32(0u, 42u, 0u, (uint32_t)layer, Lk0, Lk1);
  threefry2x32(Lk0, Lk1, 0u, (uint32_t)which, mk0, mk1);
  threefry2x32(mk0, mk1, 0u, (uint32_t)e, b1, b2);
  g_masks[mid][e] = mask_val(b1 ^ b2);
}

// ---------------- input-projection GEMM: Y[m][n] = X[m,:]·W[n,:] + bias -----
__global__ void __launch_bounds__(256, 2) gemm_xg_kernel(
    const float* __restrict__ X, const float* __restrict__ W,
    const float* __restrict__ bi, const float* __restrict__ bh,
    float* __restrict__ Y) {
  const int K = 256, N = 1024;
  __shared__ float As[32][132];
  __shared__ float Bs[32][132];
  int bm = blockIdx.y * 128, bn = blockIdx.x * 128;
  int tid = threadIdx.x;
  int tx = tid & 15, ty = tid >> 4;

  uint64_t acc[8][4];
#pragma unroll
  for (int i = 0; i < 8; i++)
#pragma unroll
    for (int j = 0; j < 4; j++) acc[i][j] = 0ull;

  for (int k0 = 0; k0 < K; k0 += 32) {
#pragma unroll
    for (int i = 0; i < 4; i++) {
      int idx = tid + i * 256;
      int row = idx >> 3;
      int kk  = (idx & 7) << 2;
      float4 va = *(const float4*)&X[(size_t)(bm + row) * K + k0 + kk];
      As[kk + 0][row] = va.x; As[kk + 1][row] = va.y;
      As[kk + 2][row] = va.z; As[kk + 3][row] = va.w;
      float4 vb = *(const float4*)&W[(size_t)(bn + row) * K + k0 + kk];
      Bs[kk + 0][row] = vb.x; Bs[kk + 1][row] = vb.y;
      Bs[kk + 2][row] = vb.z; Bs[kk + 3][row] = vb.w;
    }
    __syncthreads();
#pragma unroll
    for (int kk = 0; kk < 32; kk++) {
      float4 a0 = *(const float4*)&As[kk][ty * 8];
      float4 a1 = *(const float4*)&As[kk][ty * 8 + 4];
      ulonglong2 b0 = *(const ulonglong2*)&Bs[kk][tx * 8];
      ulonglong2 b1 = *(const ulonglong2*)&Bs[kk][tx * 8 + 4];
      float av[8] = {a0.x, a0.y, a0.z, a0.w, a1.x, a1.y, a1.z, a1.w};
#pragma unroll
      for (int i = 0; i < 8; i++) {
        uint64_t ap;
        PACKD(ap, av[i]);
        FMA2(acc[i][0], ap, b0.x);
        FMA2(acc[i][1], ap, b0.y);
        FMA2(acc[i][2], ap, b1.x);
        FMA2(acc[i][3], ap, b1.y);
      }
    }
    __syncthreads();
  }

  float bias[8];
#pragma unroll
  for (int j = 0; j < 8; j++) {
    int n = bn + tx * 8 + j;
    bias[j] = bi[n] + bh[n];
  }
#pragma unroll
  for (int i = 0; i < 8; i++) {
    float c[8];
#pragma unroll
    for (int j = 0; j < 4; j++) UNPACK2(c[2 * j], c[2 * j + 1], acc[i][j]);
    size_t base = (size_t)(bm + ty * 8 + i) * N + bn + tx * 8;
    float4 v0 = make_float4(c[0] + bias[0], c[1] + bias[1],
                            c[2] + bias[2], c[3] + bias[3]);
    float4 v1 = make_float4(c[4] + bias[4], c[5] + bias[5],
                            c[6] + bias[6], c[7] + bias[7]);
    *(float4*)&Y[base]     = v0;
    *(float4*)&Y[base + 4] = v1;
  }
}

// ---------------- persistent recurrent LSTM layer ---------------------------
// 16 clusters x 8 CTAs; cluster owns 4 batches as 2 groups of 2 (pipelined).
// CTA rank s owns units [32s,32s+32). Warp w owns units {2w,2w+1} x 4 gates.
// Lane = q*4+gate (q = 32-k slice). Weights in regs (unit-pairs packed f32x2).
// Step (per group): wait mbar -> matmul -> butterfly(q) -> warp exch ->
// finalize -> st.async h (16B/warp/rank, complete_tx) -> next group.
// hbuf[g][par]: 256 k x 2 b floats, +8B pad per 32-k block => 2112 B.
#define HB_BUF_B   2112
#define HB_G_B     (2 * HB_BUF_B)             // per group (2 parities)
#define SCR_OFF    (4 * HB_BUF_B)             // 8448
#define SCR_W_B    80                          // 64B exch + 16B hstage
#define MB_OFF     (SCR_OFF + 16 * SCR_W_B)   // 9728
#define SMEM_TOT   (MB_OFF + 32)

__global__ void __launch_bounds__(512, 1) __cluster_dims__(8, 1, 1)
lstm_layer_kernel(const float* __restrict__ xg, const float* __restrict__ Whh,
                  const float* __restrict__ mask_out,
                  const float* __restrict__ mask_h,
                  const float* __restrict__ mask_c,
                  float* __restrict__ out) {
  __shared__ __align__(16) unsigned char sm[SMEM_TOT];
  uint32_t sb = (uint32_t)__cvta_generic_to_shared(sm);

  int tid  = threadIdx.x;
  int w    = tid >> 5;
  int lane = tid & 31;
  uint32_t s;
  asm("mov.u32 %0, %%cluster_ctarank;" : "=r"(s));
  int cb = blockIdx.x >> 3;             // cluster id (batches cb*4 .. cb*4+3)

  int gate = lane & 3;
  int q    = lane >> 2;                 // 32-k slice 0..7

  // ---- weights: rows (gate, units 2w/2w+1), k in [32q, 32q+32) -------------
  uint64_t wp[32];
  {
    int R0 = gate * 256 + (int)s * 32 + 2 * w;
    const float* w0 = Whh + (size_t)R0 * 256 + q * 32;
    const float* w1 = w0 + 256;
#pragma unroll
    for (int kk = 0; kk < 32; kk++) PACK2V(wp[kk], w0[kk], w1[kk]);
  }

  // ---- zero h buffers, init mbarriers --------------------------------------
  for (int idx = tid; idx < SCR_OFF / 4; idx += 512)
    ((float*)sm)[idx] = 0.f;
  if (tid == 0) {
#pragma unroll
    for (int i = 0; i < 4; i++) MBAR_INIT(sb + MB_OFF + i * 8, 1);
  }

  // ---- finalize-role (lane<4): (u = lane>>1, b = lane&1), both groups ------
  int u = lane >> 1, b = lane & 1;
  int gu = (int)s * 32 + 2 * w + u;
  float cst[2] = {0.f, 0.f};
  float mo[2], mhv[2], mcv[2];
  size_t out_b[2];
  const float* xg_b[2];
  if (lane < 4) {
#pragma unroll
    for (int g = 0; g < 2; g++) {
      int bb = cb * 4 + g * 2 + b;
      mo[g]  = mask_out[bb * 256 + gu];
      mhv[g] = mask_h  [bb * 256 + gu];
      mcv[g] = mask_c  [bb * 256 + gu];
      out_b[g] = (size_t)bb * (T_ * H_) + gu;
      xg_b[g]  = xg + (size_t)bb * (T_ * G4_) + gu;
    }
  }

  // ---- store-role (lane<16): rank = lane>>1, piece = lane&1 ----------------
  uint32_t r_hb[2], r_mb[2];
  uint32_t src_hst = sb + SCR_OFF + w * SCR_W_B + 64 + (lane & 1) * 8;
  {
    uint32_t rk = (uint32_t)(lane >> 1) & 7;
    uint32_t dest_off =
        (uint32_t)(((int)s * 32 + 2 * w) * 8 + (int)s * 8 + (lane & 1) * 8);
#pragma unroll
    for (int g = 0; g < 2; g++) {
      r_hb[g] = mapa_smem(sb + g * HB_G_B + dest_off, rk);
      r_mb[g] = mapa_smem(sb + MB_OFF + g * 16, rk);
    }
  }

  float* scr   = (float*)(sm + SCR_OFF + w * SCR_W_B);
  uint64_t* sx = (uint64_t*)scr;

  __syncthreads();
  asm volatile("barrier.cluster.arrive.aligned;" ::: "memory");
  asm volatile("barrier.cluster.wait.aligned;"   ::: "memory");

  for (int t = 0; t < T_; t++) {
    int buf  = t & 1;
    int nbuf = buf ^ 1;
    uint32_t wpar = (uint32_t)(((t - 1) >> 1) & 1);

    // post expected bytes for the buffers written this step
    if (tid == 0) {
      MBAR_EXPECT(sb + MB_OFF + 0 * 16 + nbuf * 8, 2048u);
      MBAR_EXPECT(sb + MB_OFF + 1 * 16 + nbuf * 8, 2048u);
    }

    // prefetch gate preacts for both groups (finalize lanes)
    float xv[2][4];
    if (lane < 4) {
#pragma unroll
      for (int g = 0; g < 2; g++) {
        const float* xp = xg_b[g] + (size_t)t * G4_;
        xv[g][0] = xp[0];
        xv[g][1] = xp[256];
        xv[g][2] = xp[512];
        xv[g][3] = xp[768];
      }
    }

#pragma unroll
    for (int g = 0; g < 2; g++) {
      if (t > 0) WAIT_MBAR(sb + MB_OFF + g * 16 + buf * 8, wpar);

      // matmul over this lane's 32 k: acc0 = {u0,u1} for b0, acc1 for b1
      const float2* hbp =
          (const float2*)(sm + g * HB_G_B + buf * HB_BUF_B + q * 264);
      uint64_t a0 = 0ull, a1 = 0ull;
#pragma unroll
      for (int kk = 0; kk < 32; kk++) {
        float2 hv = hbp[kk];
        uint64_t d0, d1;
        PACKD(d0, hv.x);
        PACKD(d1, hv.y);
        FMA2(a0, wp[kk], d0);
        FMA2(a1, wp[kk], d1);
      }
      // butterfly over q (lanes stride 4)
#pragma unroll
      for (int m = 4; m <= 16; m <<= 1) {
        uint64_t o0 = __shfl_xor_sync(0xFFFFFFFFu, a0, m);
        uint64_t o1 = __shfl_xor_sync(0xFFFFFFFFu, a1, m);
        ADD2(a0, a0, o0);
        ADD2(a1, a1, o1);
      }
      if (lane < 4) {             // q==0 lanes hold gate totals
        sx[gate * 2 + 0] = a0;    // b0
        sx[gate * 2 + 1] = a1;    // b1
      }
      __syncwarp();

      if (lane < 4) {             // finalize (u, b)
        float gi = xv[g][0] + scr[(0 * 2 + b) * 2 + u];
        float gf = xv[g][1] + scr[(1 * 2 + b) * 2 + u];
        float gg = xv[g][2] + scr[(2 * 2 + b) * 2 + u];
        float go = xv[g][3] + scr[(3 * 2 + b) * 2 + u];
        float ig = fast_sigmoid(gi);
        float fg = fast_sigmoid(gf);
        float og = fast_sigmoid(go);
        float gt = fast_tanh(gg);
        float c  = fg * cst[g] + ig * gt;
        float h  = og * fast_tanh(c);
        cst[g] = c * mcv[g];
        out[out_b[g] + (size_t)t * H_] = h * mo[g];
        scr[16 + u * 2 + b] = h * mhv[g];   // hstage [unit][batch]
      }
      __syncwarp();

      if (lane < 16) {            // broadcast: 8 B piece to one rank
        uint64_t v;
        asm volatile("ld.shared.b64 %0, [%1];" : "=l"(v) : "r"(src_hst));
        uint32_t da = r_hb[g] + (uint32_t)nbuf * HB_BUF_B;
        uint32_t db = r_mb[g] + (uint32_t)nbuf * 8;
        asm volatile(
            "st.async.shared::cluster.mbarrier::complete_tx::bytes.b64 "
            "[%0], %1, [%2];"
            :: "r"(da), "l"(v), "r"(db) : "memory");
      }
      __syncwarp();               // protect scratch before other group reuses
    }
  }

  // drain the last in-flight phase (stores of t=511 into buf 0)
  {
    uint32_t fpar = (uint32_t)(((T_ - 1) >> 1) & 1);
    WAIT_MBAR(sb + MB_OFF + 0 * 16 + 0 * 8, fpar);
    WAIT_MBAR(sb + MB_OFF + 1 * 16 + 0 * 8, fpar);
  }
  asm volatile("barrier.cluster.arrive.aligned;" ::: "memory");
  asm volatile("barrier.cluster.wait.aligned;"   ::: "memory");
}

// ---------------- launcher ---------------------------------------------------
extern "C" void kernel_launch(void* const* d_in, const int* in_sizes, int n_in,
                              void* d_out, int out_size) {
  const float* x     = (const float*)d_in[0];
  const float* W_ih0 = (const float*)d_in[1];
  const float* W_hh0 = (const float*)d_in[2];
  const float* b_ih0 = (const float*)d_in[3];
  const float* b_hh0 = (const float*)d_in[4];
  const float* W_ih1 = (const float*)d_in[5];
  const float* W_hh1 = (const float*)d_in[6];
  const float* b_ih1 = (const float*)d_in[7];
  const float* b_hh1 = (const float*)d_in[8];
  float* out = (float*)d_out;

  float *xg, *y1, *masks;
  cudaGetSymbolAddress((void**)&xg, g_xg);
  cudaGetSymbolAddress((void**)&y1, g_y1);
  cudaGetSymbolAddress((void**)&masks, g_masks);

  mask_kernel<<<dim3(64, 6), 256>>>();

  gemm_xg_kernel<<<dim3(8, 256), 256>>>(x, W_ih0, b_ih0, b_hh0, xg);
  lstm_layer_kernel<<<128, 512>>>(
      xg, W_hh0, masks + 0 * 16384, masks + 1 * 16384, masks + 2 * 16384, y1);

  gemm_xg_kernel<<<dim3(8, 256), 256>>>(y1, W_ih1, b_ih1, b_hh1, xg);
  lstm_layer_kernel<<<128, 512>>>(
      xg, W_hh1, masks + 3 * 16384, masks + 4 * 16384, masks + 5 * 16384, out);
}